// round 3
// baseline (speedup 1.0000x reference)
#include <cuda_runtime.h>

// ---------------------------------------------------------------------------
// Net_40312563041045: 4-layer max-tempered MLP
//   layer(x; W, b) = 0.8 * (W @ x) + 0.2 * max_i(W[o,i]*x[b,i]) + b
// FFMA2 (fma.rn.f32x2) inner loop: the only packed-f32 op with a real SASS
// counterpart on sm_10x. 2 FFMA2 + 2 FMNMX per 2 products.
// ---------------------------------------------------------------------------

#define SPITCH 132   // smem floats per kp row (128 data + 4 pad)

__device__ __align__(16) float g_buf0[1024 * 512];
__device__ __align__(16) float g_buf1[1024 * 512];

union F4U2 { float4 f4; unsigned long long u[2]; };

__device__ __forceinline__ void ffma2_acc(unsigned long long& acc,
                                          unsigned long long a, unsigned long long b) {
    asm("fma.rn.f32x2 %0, %1, %2, %0;" : "+l"(acc) : "l"(a), "l"(b));
}
__device__ __forceinline__ unsigned long long ffma2_zero(unsigned long long a,
                                                         unsigned long long b,
                                                         unsigned long long z) {
    unsigned long long p;
    asm("fma.rn.f32x2 %0, %1, %2, %3;" : "=l"(p) : "l"(a), "l"(b), "l"(z));
    return p;
}
__device__ __forceinline__ void unpack2(unsigned long long p, float& lo, float& hi) {
    asm("mov.b64 {%0, %1}, %2;" : "=f"(lo), "=f"(hi) : "l"(p));
}

// 64x64 output tile per block, 256 threads, 4x4 register tile (K-pair packed).
// Smem per BK=16 tile: 8 kp-rows of 128 floats: [kp][m*2 + (k&1)].
__global__ __launch_bounds__(256, 1) void tempered_layer(
    const float* __restrict__ X,     // [M, K]
    const float* __restrict__ Wm,    // [N, K]
    const float* __restrict__ bias,  // [N]
    float* __restrict__ Y,           // [M, N]
    int K, int N)
{
    __shared__ __align__(16) float xs[2][8 * SPITCH];
    __shared__ __align__(16) float ws[2][8 * SPITCH];

    const int tid  = threadIdx.x;
    const int lane = tid & 31;
    const int wrp  = tid >> 5;
    // conflict-free compute mapping: within an 8-lane LDS.128 phase, tx spans
    // 4 values (32B apart -> distinct bank groups, pair-broadcast), ty spans 2.
    const int tx = (lane & 3) | ((wrp & 3) << 2);          // 0..15 (N dim)
    const int ty = ((lane >> 2) & 7) | ((wrp >> 2) << 3);  // 0..15 (M dim)

    const int row0 = blockIdx.x * 64;
    const int col0 = blockIdx.y * 64;

    // tile-load mapping: each thread loads one float4 along K
    const int lm  = tid >> 2;         // 0..63 (row within tile)
    const int lk4 = (tid & 3) << 2;   // 0,4,8,12
    const int kp0 = lk4 >> 1;         // 0,2,4,6

    const float* Xp = X  + (size_t)(row0 + lm) * K + lk4;
    const float* Wp = Wm + (size_t)(col0 + lm) * K + lk4;

    float4 xr = *(const float4*)Xp;
    float4 wr = *(const float4*)Wp;

    unsigned long long acc[4][4];
    float mxlo[4][4], mxhi[4][4];
#pragma unroll
    for (int i = 0; i < 4; ++i)
#pragma unroll
        for (int j = 0; j < 4; ++j) {
            acc[i][j]  = 0ull;                      // packed (0.0f, 0.0f)
            mxlo[i][j] = -3.402823466e38f;
            mxhi[i][j] = -3.402823466e38f;
        }

    const unsigned long long zero2 = 0ull;
    const int T = K >> 4;

    // stage tile 0 (row kp holds k-even at m*2, k-odd at m*2+1)
    {
        float* xd = &xs[0][kp0 * SPITCH + lm * 2];
        float* wd = &ws[0][kp0 * SPITCH + lm * 2];
        *(float2*)xd            = make_float2(xr.x, xr.y);
        *(float2*)(xd + SPITCH) = make_float2(xr.z, xr.w);
        *(float2*)wd            = make_float2(wr.x, wr.y);
        *(float2*)(wd + SPITCH) = make_float2(wr.z, wr.w);
    }
    __syncthreads();

    for (int t = 0; t < T; ++t) {
        if (t + 1 < T) {
            xr = *(const float4*)(Xp + (t + 1) * 16);
            wr = *(const float4*)(Wp + (t + 1) * 16);
        }

        const float* xb = xs[t & 1];
        const float* wb = ws[t & 1];
#pragma unroll
        for (int kp = 0; kp < 8; ++kp) {
            F4U2 xa0, xa1, wa0, wa1;
            xa0.f4 = *(const float4*)(xb + kp * SPITCH + 8 * ty);
            xa1.f4 = *(const float4*)(xb + kp * SPITCH + 8 * ty + 4);
            wa0.f4 = *(const float4*)(wb + kp * SPITCH + 8 * tx);
            wa1.f4 = *(const float4*)(wb + kp * SPITCH + 8 * tx + 4);
            unsigned long long x2[4] = {xa0.u[0], xa0.u[1], xa1.u[0], xa1.u[1]};
            unsigned long long w2[4] = {wa0.u[0], wa0.u[1], wa1.u[0], wa1.u[1]};
#pragma unroll
            for (int i = 0; i < 4; ++i)
#pragma unroll
                for (int j = 0; j < 4; ++j) {
                    unsigned long long p = ffma2_zero(x2[i], w2[j], zero2);
                    ffma2_acc(acc[i][j], x2[i], w2[j]);
                    float plo, phi;
                    unpack2(p, plo, phi);
                    mxlo[i][j] = fmaxf(mxlo[i][j], plo);
                    mxhi[i][j] = fmaxf(mxhi[i][j], phi);
                }
        }

        if (t + 1 < T) {
            float* xd = &xs[(t + 1) & 1][kp0 * SPITCH + lm * 2];
            float* wd = &ws[(t + 1) & 1][kp0 * SPITCH + lm * 2];
            *(float2*)xd            = make_float2(xr.x, xr.y);
            *(float2*)(xd + SPITCH) = make_float2(xr.z, xr.w);
            *(float2*)wd            = make_float2(wr.x, wr.y);
            *(float2*)(wd + SPITCH) = make_float2(wr.z, wr.w);
        }
        __syncthreads();
    }

    // epilogue: out = 0.8*(acc_lo+acc_hi) + 0.2*max(mxlo,mxhi) + bias
    const int cbase = col0 + 4 * tx;
    float4 bv = *(const float4*)(bias + cbase);
    float ba[4] = {bv.x, bv.y, bv.z, bv.w};
#pragma unroll
    for (int i = 0; i < 4; ++i) {
        const int r = row0 + 4 * ty + i;
        float o[4];
#pragma unroll
        for (int j = 0; j < 4; ++j) {
            float alo, ahi;
            unpack2(acc[i][j], alo, ahi);
            float lin = alo + ahi;
            float mx  = fmaxf(mxlo[i][j], mxhi[i][j]);
            o[j] = 0.8f * lin + 0.2f * mx + ba[j];
        }
        *(float4*)(Y + (size_t)r * N + cbase) = make_float4(o[0], o[1], o[2], o[3]);
    }
}

// Final layer: OUT=1. One warp per batch row, 4 independent accumulator
// chains with front-batched float4 loads (MLP=8).
__global__ __launch_bounds__(256) void out_layer(
    const float* __restrict__ H,   // [B, K]
    const float* __restrict__ w4,  // [K]
    const float* __restrict__ b4,  // [1]
    float* __restrict__ out,       // [B]
    int K)
{
    const int warp = (blockIdx.x * blockDim.x + threadIdx.x) >> 5;
    const int lane = threadIdx.x & 31;

    const float4* h4  = (const float4*)(H + (size_t)warp * K);
    const float4* w44 = (const float4*)w4;
    const int K4 = K >> 2;   // 128 for K=512 -> exactly 4 chunks of 32

    float s0 = 0.f, s1 = 0.f, s2 = 0.f, s3 = 0.f;
    float m0 = -3.402823466e38f, m1 = m0, m2 = m0, m3 = m0;

    int i0 = lane, i1 = lane + 32, i2 = lane + 64, i3 = lane + 96;
    for (; i3 < K4; i0 += 128, i1 += 128, i2 += 128, i3 += 128) {
        float4 h0 = h4[i0], h1 = h4[i1], h2 = h4[i2], h3 = h4[i3];
        float4 w0 = w44[i0], w1 = w44[i1], w2 = w44[i2], w3 = w44[i3];
        float a0 = w0.x*h0.x, a1 = w0.y*h0.y, a2 = w0.z*h0.z, a3 = w0.w*h0.w;
        s0 += (a0+a1)+(a2+a3); m0 = fmaxf(m0, fmaxf(fmaxf(a0,a1), fmaxf(a2,a3)));
        float c0 = w1.x*h1.x, c1 = w1.y*h1.y, c2 = w1.z*h1.z, c3 = w1.w*h1.w;
        s1 += (c0+c1)+(c2+c3); m1 = fmaxf(m1, fmaxf(fmaxf(c0,c1), fmaxf(c2,c3)));
        float d0 = w2.x*h2.x, d1 = w2.y*h2.y, d2 = w2.z*h2.z, d3 = w2.w*h2.w;
        s2 += (d0+d1)+(d2+d3); m2 = fmaxf(m2, fmaxf(fmaxf(d0,d1), fmaxf(d2,d3)));
        float e0 = w3.x*h3.x, e1 = w3.y*h3.y, e2 = w3.z*h3.z, e3 = w3.w*h3.w;
        s3 += (e0+e1)+(e2+e3); m3 = fmaxf(m3, fmaxf(fmaxf(e0,e1), fmaxf(e2,e3)));
    }
    for (; i0 < K4; i0 += 32) {   // remainder (not taken for K=512)
        float4 hv = h4[i0]; float4 wv = w44[i0];
        float a0 = wv.x*hv.x, a1 = wv.y*hv.y, a2 = wv.z*hv.z, a3 = wv.w*hv.w;
        s0 += (a0+a1)+(a2+a3); m0 = fmaxf(m0, fmaxf(fmaxf(a0,a1), fmaxf(a2,a3)));
    }

    float s = (s0 + s1) + (s2 + s3);
    float m = fmaxf(fmaxf(m0, m1), fmaxf(m2, m3));
#pragma unroll
    for (int o = 16; o > 0; o >>= 1) {
        s += __shfl_xor_sync(0xFFFFFFFFu, s, o);
        m = fmaxf(m, __shfl_xor_sync(0xFFFFFFFFu, m, o));
    }
    if (lane == 0) out[warp] = 0.8f * s + 0.2f * m + b4[0];
}

extern "C" void kernel_launch(void* const* d_in, const int* in_sizes, int n_in,
                              void* d_out, int out_size)
{
    const float* x  = (const float*)d_in[0];
    const float* W1 = (const float*)d_in[1];
    const float* b1 = (const float*)d_in[2];
    const float* W2 = (const float*)d_in[3];
    const float* b2 = (const float*)d_in[4];
    const float* W3 = (const float*)d_in[5];
    const float* b3 = (const float*)d_in[6];
    const float* W4 = (const float*)d_in[7];
    const float* b4 = (const float*)d_in[8];

    const int Wd = in_sizes[2];            // hidden width = 512
    const int IN = in_sizes[1] / Wd;       // 256
    const int B  = in_sizes[0] / IN;       // 1024

    float *h0, *h1;
    cudaGetSymbolAddress((void**)&h0, g_buf0);
    cudaGetSymbolAddress((void**)&h1, g_buf1);

    dim3 grid(B / 64, Wd / 64);
    tempered_layer<<<grid, 256>>>(x,  W1, b1, h0, IN, Wd);
    tempered_layer<<<grid, 256>>>(h0, W2, b2, h1, Wd, Wd);
    tempered_layer<<<grid, 256>>>(h1, W3, b3, h0, Wd, Wd);
    out_layer<<<B / 8, 256>>>(h0, W4, b4, (float*)d_out, Wd);
}